// round 11
// baseline (speedup 1.0000x reference)
#include <cuda_runtime.h>
#include <math.h>

#define NS 4096
#define NT 4096
#define RPB 32
#define TPB 128
typedef unsigned long long ull;

__device__ double g_acc = 0.0;
__device__ unsigned int g_cnt = 0;

// ---- f32x2 packed helpers (sm_103a) ----
__device__ __forceinline__ ull pk2(float lo, float hi) {
    ull r; asm("mov.b64 %0,{%1,%2};" : "=l"(r) : "f"(lo), "f"(hi)); return r;
}
__device__ __forceinline__ float2 unpk2(ull v) {
    float2 f; asm("mov.b64 {%0,%1},%2;" : "=f"(f.x), "=f"(f.y) : "l"(v)); return f;
}
__device__ __forceinline__ ull fma2_(ull a, ull b, ull c) {
    ull d; asm("fma.rn.f32x2 %0,%1,%2,%3;" : "=l"(d) : "l"(a), "l"(b), "l"(c)); return d;
}
__device__ __forceinline__ ull add2_(ull a, ull b) {
    ull d; asm("add.rn.f32x2 %0,%1,%2;" : "=l"(d) : "l"(a), "l"(b)); return d;
}
__device__ __forceinline__ ull sub2_(ull a, ull b) {
    ull d; asm("sub.rn.f32x2 %0,%1,%2;" : "=l"(d) : "l"(a), "l"(b)); return d;
}
__device__ __forceinline__ ull mul2_(ull a, ull b) {
    ull d; asm("mul.rn.f32x2 %0,%1,%2;" : "=l"(d) : "l"(a), "l"(b)); return d;
}
__device__ __forceinline__ ull clamp2_(ull v) {
    float2 f = unpk2(v);
    f.x = fminf(fmaxf(f.x, -100.0f), 100.0f);
    f.y = fminf(fmaxf(f.y, -100.0f), 100.0f);
    return pk2(f.x, f.y);
}

// one grid row: um = row i-1, cc = row i, up = row i+1 (this thread's 4 cols)
__device__ __forceinline__ void row_accum(
    float4 um, float4 cc, float4 up, float left, float right,
    ull a2, ull nb2, ull nc2, ull nc1,
    ull M2, ull IDT2s,
    bool maskL, bool maskR, bool valid,
    ull& acc0, ull& acc1)
{
    ull um0 = pk2(um.x, um.y), um1 = pk2(um.z, um.w);
    ull cc0 = pk2(cc.x, cc.y), cc1 = pk2(cc.z, cc.w);
    ull up0 = pk2(up.x, up.y), up1 = pk2(up.z, up.w);
    ull cL  = pk2(left, cc.x);
    ull yz  = pk2(cc.y, cc.z);
    ull cR  = pk2(cc.w, right);

    ull Du0  = sub2_(up0, um0);
    ull Du1  = sub2_(up1, um1);
    ull Duu0 = fma2_(cc0, M2, add2_(up0, um0));
    ull Duu1 = fma2_(cc1, M2, add2_(up1, um1));
    ull VSS0 = clamp2_(fma2_(Duu0, a2, mul2_(Du0, nb2)));
    ull VSS1 = clamp2_(fma2_(Duu1, a2, mul2_(Du1, nb2)));
    ull Dt0  = sub2_(yz, cL);
    ull Dt1  = sub2_(cR, yz);

    ull r0 = fma2_(Dt0, IDT2s, cc0);
    r0 = fma2_(VSS0, nc2, r0);
    r0 = fma2_(Du0,  nc1, r0);
    ull r1 = fma2_(Dt1, IDT2s, cc1);
    r1 = fma2_(VSS1, nc2, r1);
    r1 = fma2_(Du1,  nc1, r1);

    if (maskL) { float2 f = unpk2(r0); r0 = pk2(0.0f, f.y); }
    if (maskR) { float2 f = unpk2(r1); r1 = pk2(f.x, 0.0f); }
    if (valid) {
        acc0 = fma2_(r0, r0, acc0);
        acc1 = fma2_(r1, r1, acc1);
    }
}

__global__ __launch_bounds__(TPB, 7) void loss_kernel(const float* __restrict__ V,
                                                      float C1, float dL,
                                                      float* __restrict__ out,
                                                      unsigned int nblocks)
{
    __shared__ ulonglong2 scA[RPB];   // {a2, -b2}
    __shared__ ulonglong2 scB[RPB];   // {-c2*0.4, -c1*0.4}
    __shared__ double ws[TPB / 32];

    const int tid  = threadIdx.x;
    const int lane = tid & 31;
    const int bx   = blockIdx.x;
    const int by   = blockIdx.y;
    const int j0   = bx * (TPB * 4) + tid * 4;   // 4-col chunk
    const int r0b  = by * RPB;

    const float INV2DT = 4095.0f / 0.04f;
    const float INV2DU = 4095.0f * 0.5f;
    const float INVDU2 = 4095.0f * 4095.0f;
    const float RS = 0.4f;

    if (tid < RPB) {
        int i = r0b + tid;
        float u   = (float)i * (1.0f / 4095.0f);
        float L   = fmaf(dL, u, C1);
        float L2  = L * L;
        float S   = fmaf(30.0f, fmaf(L2 * L, (1.0f / 6.0f), L), 100.0f);
        float Sn  = S * (1.0f / 300.0f);
        float Su  = 0.1f * dL * fmaf(0.5f, L2, 1.0f);
        float Suu = 0.1f * dL * dL * L;
        float rSu  = 1.0f / Su;
        float rSu2 = rSu * rSu;
        float a  = INVDU2 * rSu2;
        float b  = INV2DU * Suu * rSu2 * rSu;
        float c2 = Sn * Sn * RS;
        float c1 = 2.5f * Sn * INV2DU * rSu * RS;
        scA[tid] = make_ulonglong2(pk2(a, a),     pk2(-b, -b));
        scB[tid] = make_ulonglong2(pk2(-c2, -c2), pk2(-c1, -c1));
    }
    __syncthreads();

    const bool maskL = (j0 == 0);
    const bool maskR = (j0 + 3 == NT - 1);
    const ull M2    = pk2(-2.0f, -2.0f);
    const ull IDT2s = pk2(INV2DT * RS, INV2DT * RS);

    const int jL = (j0 > 0) ? j0 - 1 : 0;
    const int jR = (j0 + 4 < NT) ? j0 + 4 : NT - 1;
    const bool isL = (lane == 0);
    const bool isR = (lane == 31);

    // rolling pointers (strength-reduced addressing)
    const float* pc = V + j0 + (size_t)r0b * NT;          // row i (center)
    const float* pm = pc - ((r0b > 0) ? NT : 0);          // row i-1 seed
    const float* peL = V + jL + (size_t)r0b * NT;         // edge row i
    const float* peR = V + jR + (size_t)r0b * NT;

    float4 vm4 = *(const float4*)pm;
    float4 vc4 = *(const float4*)pc;

    ull acc0 = 0ull, acc1 = 0ull;

    #pragma unroll 1
    for (int i = r0b; i < r0b + RPB; i += 4) {
        // front-batched: 4 next rows (independent LDG.128)
        float4 v1 = *(const float4*)(pc + NT);
        float4 v2 = *(const float4*)(pc + 2 * NT);
        float4 v3 = *(const float4*)(pc + 3 * NT);
        const float* p4 = (i + 4 < NS) ? (pc + 4 * NT) : (pc + 3 * NT);
        float4 v4 = *(const float4*)p4;

        float eL0 = 0.f, eL1 = 0.f, eL2 = 0.f, eL3 = 0.f;
        float eR0 = 0.f, eR1 = 0.f, eR2 = 0.f, eR3 = 0.f;
        if (isL) {
            eL0 = __ldg(peL);
            eL1 = __ldg(peL + NT);
            eL2 = __ldg(peL + 2 * NT);
            eL3 = __ldg(peL + 3 * NT);
        }
        if (isR) {
            eR0 = __ldg(peR);
            eR1 = __ldg(peR + NT);
            eR2 = __ldg(peR + 2 * NT);
            eR3 = __ldg(peR + 3 * NT);
        }

        float l0 = __shfl_up_sync(0xffffffffu, vc4.w, 1);
        float r0 = __shfl_down_sync(0xffffffffu, vc4.x, 1);
        float l1 = __shfl_up_sync(0xffffffffu, v1.w, 1);
        float r1 = __shfl_down_sync(0xffffffffu, v1.x, 1);
        float l2 = __shfl_up_sync(0xffffffffu, v2.w, 1);
        float r2 = __shfl_down_sync(0xffffffffu, v2.x, 1);
        float l3 = __shfl_up_sync(0xffffffffu, v3.w, 1);
        float r3 = __shfl_down_sync(0xffffffffu, v3.x, 1);
        if (isL) { l0 = eL0; l1 = eL1; l2 = eL2; l3 = eL3; }
        if (isR) { r0 = eR0; r1 = eR1; r2 = eR2; r3 = eR3; }

        const int k = i - r0b;
        ulonglong2 cA0 = scA[k],     cB0 = scB[k];
        ulonglong2 cA1 = scA[k + 1], cB1 = scB[k + 1];
        ulonglong2 cA2 = scA[k + 2], cB2 = scB[k + 2];
        ulonglong2 cA3 = scA[k + 3], cB3 = scB[k + 3];

        bool valid0 = (i != 0);
        bool valid3 = (i + 3 != NS - 1);

        row_accum(vm4, vc4, v1, l0, r0, cA0.x, cA0.y, cB0.x, cB0.y,
                  M2, IDT2s, maskL, maskR, valid0, acc0, acc1);
        row_accum(vc4, v1, v2, l1, r1, cA1.x, cA1.y, cB1.x, cB1.y,
                  M2, IDT2s, maskL, maskR, true, acc0, acc1);
        row_accum(v1, v2, v3, l2, r2, cA2.x, cA2.y, cB2.x, cB2.y,
                  M2, IDT2s, maskL, maskR, true, acc0, acc1);
        row_accum(v2, v3, v4, l3, r3, cA3.x, cA3.y, cB3.x, cB3.y,
                  M2, IDT2s, maskL, maskR, valid3, acc0, acc1);

        vm4 = v3; vc4 = v4;
        pc  += 4 * NT;
        peL += 4 * NT;
        peR += 4 * NT;
    }

    float2 a0 = unpk2(acc0), a1 = unpk2(acc1);
    double p = ((double)a0.x + (double)a0.y + (double)a1.x + (double)a1.y)
             * (6.25 / (4094.0 * 4094.0));

    // ---- BC / TC tails ----
    if (by == 0 && bx == 0) {
        const float* rowp = V + (size_t)(NS - 1) * NT;
        double s = 0.0;
        for (int t = tid; t < NT; t += TPB) {
            float tn = (float)t * (1.0f / 4095.0f);
            float target = 1.0f - (1.0f / 3.0f) * expf(-0.05f * (1.0f - tn));
            float d = rowp[t] - target;
            s += (double)(d * d);
        }
        p += s * (10.0 / (double)NT);
    } else if (by == 0 && bx == 1) {
        double s = 0.0;
        for (int si = tid; si < NS; si += TPB) {
            float u  = (float)si * (1.0f / 4095.0f);
            float x  = 50.0f * (u - (1.0f / 3.0f));
            float sp = (fmaxf(x, 0.0f) + log1pf(expf(-fabsf(x)))) * (1.0f / 50.0f);
            float d  = V[(size_t)si * NT + (NT - 1)] - sp;
            float ad = fabsf(d);
            float h  = (ad < 0.01f) ? 0.5f * d * d : 0.01f * (ad - 0.005f);
            s += (double)h;
        }
        p += s * (10.0 / (double)NS);
    }

    // ---- block reduce (double) ----
    #pragma unroll
    for (int o = 16; o > 0; o >>= 1)
        p += __shfl_down_sync(0xffffffffu, p, o);
    if (lane == 0) ws[tid >> 5] = p;
    __syncthreads();

    if (tid == 0) {
        double s = 0.0;
        #pragma unroll
        for (int k = 0; k < TPB / 32; ++k) s += ws[k];
        atomicAdd(&g_acc, s);
        __threadfence();
        unsigned int t = atomicAdd(&g_cnt, 1u);
        if (t == nblocks - 1u) {
            double total = atomicAdd(&g_acc, 0.0);
            out[0] = (float)total;
            g_acc = 0.0;
            __threadfence();
            g_cnt = 0u;
        }
    }
}

// Host-side: hyperbolic root of depressed cubic (CubicStretching)
static double solve_depressed_cubic(double Q)
{
    const double p = 6.0;
    const double q = 6.0 * Q;
    double sp = sqrt(p);
    double arg = fabs(q) / (2.0 * p * sp / (3.0 * sqrt(3.0)));
    if (arg < 1.0) arg = 1.0;
    double c = 2.0 * sp * cosh(acosh(arg) / 3.0);
    return (q >= 0.0) ? -c : c;
}

extern "C" void kernel_launch(void* const* d_in, const int* in_sizes, int n_in,
                              void* d_out, int out_size)
{
    const float* V = (const float*)d_in[0];
    float* out = (float*)d_out;

    const double C1 = solve_depressed_cubic((100.0 - 0.0)   / 30.0);
    const double C2 = solve_depressed_cubic((100.0 - 300.0) / 30.0);
    const float C1f = (float)C1;
    const float dLf = (float)(C2 - C1);

    dim3 grid(NT / (TPB * 4), NS / RPB);   // (8, 128) = 1024 blocks
    loss_kernel<<<grid, TPB>>>(V, C1f, dLf, out, 1024u);
}